// round 16
// baseline (speedup 1.0000x reference)
#include <cuda_runtime.h>
#include <cuda_bf16.h>
#include <mma.h>
#include <math.h>
#include <stdint.h>

using namespace nvcuda;

#define NN 50000          // nodes
#define NPAD 50048        // padded to 128
#define NF 128            // feature width
#define NH 256            // hidden width
#define EMAX 800000
#define PMAX 100000
#define SCAN_B 1024
#define NBLK ((NN + SCAN_B - 1) / SCAN_B)   // 49

// ---- scratch (device globals; no allocation allowed) ----
__device__ int   g_eidx[EMAX];
__device__ int   g_cnt [NN + 64];           // tail [NN..NN+63] = scan flags
__device__ int   g_cur [NN];                // fill cursors (init = rowptr)
__device__ int   g_rowptr[NN + 1];
__device__ int   g_ma  [PMAX];
__device__ int   g_mb  [PMAX];
__device__ float g_dinv[NN];
__device__ __nv_bfloat16 g_Wh[(size_t)NF * NH];    // hi(W1)
__device__ __nv_bfloat16 g_Wl[(size_t)NF * NH];    // lo(W1)
__device__ float g_ta  [NN];                // relu(Y1@W1+b1) @ wa
__device__ float g_tb  [NN];
__device__ float g_u   [NN];
__device__ float g_v   [NN];
__device__ float g_wa  [NH];                // W2 @ Wl[0:128]
__device__ float g_wb  [NH];                // W2 @ Wl[128:256]
__device__ float g_ca, g_cb;

// ---------------------------------------------------- prologue kernels
// Per-thread dtype sniff: int64 node ids are all in [0, NN); int32 data
// viewed as int64 fuses random pairs into huge values. 8 samples => certain.
__device__ __forceinline__ int sniff_is64(const void* p_) {
    const long long* p = (const long long*)p_;
    int ok = 1;
#pragma unroll
    for (int i = 0; i < 8; i++) {
        long long v = p[i];
        if (v < 0 || v >= NN) ok = 0;
    }
    return ok;
}

// blocks [0,EB): edge degree count; [EB,EB+PB): mask; EB+PB: collapsed
// layer-2 weights; EB+PB+1: W1 bf16 hi/lo split
__global__ void k_convert(const void* __restrict__ ei, int E,
                          const void* __restrict__ mask, int P, int EB, int PB,
                          const float* __restrict__ W1,
                          const float* __restrict__ W2,
                          const float* __restrict__ b2,
                          const float* __restrict__ Wl) {
    int b = blockIdx.x;
    if (b < EB) {
        int e = b * blockDim.x + threadIdx.x;
        if (e >= E) return;
        int c;
        if (sniff_is64(ei)) c = (int)((const long long*)ei)[(size_t)E + e];
        else                c = ((const int*)ei)[E + e];
        atomicAdd(&g_cnt[c], 1);
    } else if (b < EB + PB) {
        int i = (b - EB) * blockDim.x + threadIdx.x;
        if (i >= P) return;
        int a, c;
        if (sniff_is64(mask)) {
            const long long* p = (const long long*)mask;
            a = (int)p[(size_t)i * 2 + 0];
            c = (int)p[(size_t)i * 2 + 1];
        } else {
            const int* p = (const int*)mask;
            a = p[i * 2 + 0];
            c = p[i * 2 + 1];
        }
        g_ma[i] = a;
        g_mb[i] = c;
    } else if (b == EB + PB) {
        // collapsed layer-2 weights: wa = W2@Wl_a, wb = W2@Wl_b, ca/cb
        int k = threadIdx.x;                // 0..255
        float sa = 0.f, sb = 0.f;
#pragma unroll 8
        for (int f = 0; f < NF; f++) {
            float w = W2[k * NF + f];
            sa += w * Wl[f];
            sb += w * Wl[NF + f];
        }
        g_wa[k] = sa;
        g_wb[k] = sb;
        __shared__ float ra[NH], rb[NH];
        ra[k] = (k < NF) ? b2[k] * Wl[k] : 0.f;
        rb[k] = (k < NF) ? b2[k] * Wl[NF + k] : 0.f;
        __syncthreads();
        for (int s = NH / 2; s > 0; s >>= 1) {
            if (k < s) { ra[k] += ra[k + s]; rb[k] += rb[k + s]; }
            __syncthreads();
        }
        if (k == 0) { g_ca = ra[0]; g_cb = rb[0]; }
    } else {
        // split W1 into bf16 hi/lo
        for (int idx = threadIdx.x; idx < NF * NH; idx += blockDim.x) {
            float v = W1[idx];
            __nv_bfloat16 h = __float2bfloat16(v);
            g_Wh[idx] = h;
            g_Wl[idx] = __float2bfloat16(v - __bfloat162float(h));
        }
    }
}

// --------------- fused scan: local scan + decoupled lookback + outputs
// 49 blocks (all co-resident). Publishes agg+1 into g_cnt[NN+b]; each block
// spin-reads all predecessors. Writes rowptr, cur (=rowptr), dinv.
__global__ __launch_bounds__(SCAN_B)
void k_scan(int E) {
    __shared__ int sh[SCAN_B];
    __shared__ int sbase[32];
    int t = threadIdx.x;
    int b = blockIdx.x;
    int idx = b * SCAN_B + t;
    int v = (idx < NN) ? g_cnt[idx] : 0;
    sh[t] = v;
    __syncthreads();
    for (int off = 1; off < SCAN_B; off <<= 1) {
        int add = (t >= off) ? sh[t - off] : 0;
        __syncthreads();
        sh[t] += add;
        __syncthreads();
    }
    int excl = sh[t] - v;
    if (t == SCAN_B - 1)
        atomicExch(&g_cnt[NN + b], sh[t] + 1);
    int part = 0;
    if (t < b) {
        volatile int* f = &g_cnt[NN + t];
        int x;
        while ((x = *f) == 0) { }
        part = x - 1;
    }
    if (t < 64) {
#pragma unroll
        for (int o = 16; o > 0; o >>= 1)
            part += __shfl_xor_sync(0xffffffffu, part, o);
        if ((t & 31) == 0) sbase[t >> 5] = part;
    }
    __syncthreads();
    int base = sbase[0] + sbase[1];
    if (idx < NN) {
        int rp = excl + base;
        g_rowptr[idx] = rp;
        g_cur[idx]    = rp;
        g_dinv[idx]   = rsqrtf((float)g_cnt[idx] + 1.0f);
    }
    if (b == 0 && t == 0) g_rowptr[NN] = E;
}

// fill reads the raw edge buffer directly (no row/col scratch)
__global__ void k_fill(const void* __restrict__ ei, int E) {
    int e = blockIdx.x * blockDim.x + threadIdx.x;
    if (e >= E) return;
    int r, c;
    if (sniff_is64(ei)) {
        const long long* p = (const long long*)ei;
        r = (int)p[e];
        c = (int)p[(size_t)E + e];
    } else {
        const int* p = (const int*)ei;
        r = p[e];
        c = p[E + e];
    }
    int pos = atomicAdd(&g_cur[c], 1);
    g_eidx[pos] = r;
}

// ======== fused: CSR gather -> split-bf16 smem -> wmma GEMM -> dual dot
// CTA: 128 rows; gathers its rows from X directly into smem A tiles, then
// computes relu(Y1@W1 + b1) dot wa/wb over all 256 cols (two 128-col
// halves of B staged in turn). D = Ah*Bh + Ah*Bl + Al*Bh, fp32 accum.
#define LDA 136                              // bf16 elems per smem row (pad)
#define SM_A    (2 * 128 * LDA * 2)          // Ah + Al = 69632 B
#define SM_B    (2 * 128 * LDA * 2)          // Bh + Bl = 69632 B (also Csm)
#define SM_WMMA (SM_A + SM_B)                // 139264 B

__global__ __launch_bounds__(256, 1)
void k_gemm_fused(const float* __restrict__ X, const float* __restrict__ b1,
                  int M) {
    extern __shared__ char smc[];
    __nv_bfloat16* Ah = (__nv_bfloat16*)smc;
    __nv_bfloat16* Al = Ah + 128 * LDA;
    __nv_bfloat16* Bh = (__nv_bfloat16*)(smc + SM_A);
    __nv_bfloat16* Bl = Bh + 128 * LDA;
    float* Csm = (float*)(smc + SM_A);       // overlays B after compute

    int tid = threadIdx.x;
    int rowBlock = blockIdx.x * 128;
    int w = tid >> 5;
    int lane = tid & 31;
    int wr = w >> 2, wc = w & 3;             // 2 row-groups x 4 col-groups
    int er = tid >> 1, eh = tid & 1;         // epilogue: 2 threads / row

    // ---- phase 1: gather this CTA's 128 rows into Ah/Al (warp/node) ----
    for (int i = 0; i < 16; i++) {
        int rl = w * 16 + i;                 // local row 0..127
        int node = rowBlock + rl;
        float4 acc = make_float4(0.f, 0.f, 0.f, 0.f);
        if (node < NN) {
            float dc = g_dinv[node];
            float4 v = ((const float4*)(X + (size_t)node * NF))[lane];
            float ws = dc * dc;
            acc.x = ws * v.x; acc.y = ws * v.y;
            acc.z = ws * v.z; acc.w = ws * v.w;
            int beg = g_rowptr[node];
            int end = g_rowptr[node + 1];
#pragma unroll 8
            for (int j = beg; j < end; j++) {
                int r = __ldg(&g_eidx[j]);
                float ww = __ldg(&g_dinv[r]) * dc;
                float4 u = ((const float4*)(X + (size_t)r * NF))[lane];
                acc.x += ww * u.x; acc.y += ww * u.y;
                acc.z += ww * u.z; acc.w += ww * u.w;
            }
        }
        __nv_bfloat16 h0 = __float2bfloat16(acc.x);
        __nv_bfloat16 h1 = __float2bfloat16(acc.y);
        __nv_bfloat16 h2 = __float2bfloat16(acc.z);
        __nv_bfloat16 h3 = __float2bfloat16(acc.w);
        __nv_bfloat16 l0 = __float2bfloat16(acc.x - __bfloat162float(h0));
        __nv_bfloat16 l1 = __float2bfloat16(acc.y - __bfloat162float(h1));
        __nv_bfloat16 l2 = __float2bfloat16(acc.z - __bfloat162float(h2));
        __nv_bfloat16 l3 = __float2bfloat16(acc.w - __bfloat162float(h3));
        __nv_bfloat162 hp0 = __halves2bfloat162(h0, h1);
        __nv_bfloat162 hp1 = __halves2bfloat162(h2, h3);
        __nv_bfloat162 lp0 = __halves2bfloat162(l0, l1);
        __nv_bfloat162 lp1 = __halves2bfloat162(l2, l3);
        *(uint2*)(Ah + rl * LDA + lane * 4) =
            make_uint2(*(uint32_t*)&hp0, *(uint32_t*)&hp1);
        *(uint2*)(Al + rl * LDA + lane * 4) =
            make_uint2(*(uint32_t*)&lp0, *(uint32_t*)&lp1);
    }

    float da = 0.f, db = 0.f;

#pragma unroll
    for (int half = 0; half < 2; half++) {
        int colBlock = half * 128;
        // stage B for this half
        for (int idx = tid; idx < 128 * 16; idx += 256) {
            int k = idx >> 4, c8 = (idx & 15) << 3;
            size_t g = (size_t)k * NH + colBlock + c8;
            *(uint4*)(Bh + k * LDA + c8) = *(const uint4*)(g_Wh + g);
            *(uint4*)(Bl + k * LDA + c8) = *(const uint4*)(g_Wl + g);
        }
        __syncthreads();

        wmma::fragment<wmma::accumulator, 16, 16, 16, float> C[4][2];
#pragma unroll
        for (int i = 0; i < 4; i++)
#pragma unroll
            for (int j = 0; j < 2; j++) wmma::fill_fragment(C[i][j], 0.0f);

        for (int ks = 0; ks < 128; ks += 16) {
            wmma::fragment<wmma::matrix_a, 16, 16, 16, __nv_bfloat16, wmma::row_major> ah[4], al[4];
            wmma::fragment<wmma::matrix_b, 16, 16, 16, __nv_bfloat16, wmma::row_major> bh[2], bl[2];
#pragma unroll
            for (int i = 0; i < 4; i++) {
                wmma::load_matrix_sync(ah[i], Ah + (wr * 64 + i * 16) * LDA + ks, LDA);
                wmma::load_matrix_sync(al[i], Al + (wr * 64 + i * 16) * LDA + ks, LDA);
            }
#pragma unroll
            for (int j = 0; j < 2; j++) {
                wmma::load_matrix_sync(bh[j], Bh + ks * LDA + wc * 32 + j * 16, LDA);
                wmma::load_matrix_sync(bl[j], Bl + ks * LDA + wc * 32 + j * 16, LDA);
            }
#pragma unroll
            for (int i = 0; i < 4; i++)
#pragma unroll
                for (int j = 0; j < 2; j++) {
                    wmma::mma_sync(C[i][j], ah[i], bh[j], C[i][j]);
                    wmma::mma_sync(C[i][j], ah[i], bl[j], C[i][j]);
                    wmma::mma_sync(C[i][j], al[i], bh[j], C[i][j]);
                }
        }
        __syncthreads();                      // B reads done

#pragma unroll
        for (int i = 0; i < 4; i++)
#pragma unroll
            for (int j = 0; j < 2; j++)
                wmma::store_matrix_sync(Csm + (wr * 64 + i * 16) * LDA + wc * 32 + j * 16,
                                        C[i][j], LDA, wmma::mem_row_major);
        __syncthreads();

        // epilogue: relu(C + b1) dot wa/wb
        int cbase = eh * 64;
#pragma unroll 8
        for (int c = 0; c < 64; c++) {
            int col = colBlock + cbase + c;
            float vv = fmaxf(Csm[er * LDA + cbase + c] + __ldg(&b1[col]), 0.f);
            da += vv * g_wa[col];
            db += vv * g_wb[col];
        }
        __syncthreads();                      // Csm reads done (before restage)
    }

    da += __shfl_xor_sync(0xffffffffu, da, 1);
    db += __shfl_xor_sync(0xffffffffu, db, 1);
    if (eh == 0) {
        int row = rowBlock + er;
        if (row < M) { g_ta[row] = da; g_tb[row] = db; }
    }
}

// ------------------------------------------- scalar propagation (layer 2)
__global__ void k_gather_scalar() {
    int n = blockIdx.x * blockDim.x + threadIdx.x;
    if (n >= NN) return;
    float dc = g_dinv[n];
    float sa = dc * g_ta[n];
    float sb = dc * g_tb[n];
    int beg = g_rowptr[n], end = g_rowptr[n + 1];
    for (int j = beg; j < end; j++) {
        int r = __ldg(&g_eidx[j]);
        float w = __ldg(&g_dinv[r]);
        sa += w * __ldg(&g_ta[r]);
        sb += w * __ldg(&g_tb[r]);
    }
    g_u[n] = dc * sa + g_ca;
    g_v[n] = dc * sb + g_cb;
}

__global__ void k_pairs(const float* __restrict__ bl,
                        float* __restrict__ out, int P) {
    int p = blockIdx.x * blockDim.x + threadIdx.x;
    if (p >= P) return;
    float s = g_u[g_ma[p]] + g_v[g_mb[p]] + bl[0];
    out[p] = 1.0f / (1.0f + expf(-s));
}

// ------------------------------------------------------------------ launch
extern "C" void kernel_launch(void* const* d_in, const int* in_sizes, int n_in,
                              void* d_out, int out_size) {
    const void*  ei   = d_in[0];
    const float* X    = (const float*)d_in[1];
    const void*  mask = d_in[2];
    const float* W1   = (const float*)d_in[3];
    const float* b1   = (const float*)d_in[4];
    const float* W2   = (const float*)d_in[5];
    const float* b2   = (const float*)d_in[6];
    const float* Wl   = (const float*)d_in[7];
    const float* bl   = (const float*)d_in[8];
    float* out = (float*)d_out;

    int E = in_sizes[0] / 2;
    int P = out_size;

    cudaFuncSetAttribute(k_gemm_fused,
                         cudaFuncAttributeMaxDynamicSharedMemorySize, SM_WMMA);

    void* cnt_addr = nullptr;
    cudaGetSymbolAddress(&cnt_addr, g_cnt);

    const int T = 256;
    int EB = (E + T - 1) / T;
    int PB = (P + T - 1) / T;

    // zero degree counts + scan flags in one async memset (graph-capturable)
    cudaMemsetAsync(cnt_addr, 0, sizeof(int) * (NN + 64), 0);

    k_convert<<<EB + PB + 2, T>>>(ei, E, mask, P, EB, PB, W1, W2, b2, Wl);
    k_scan   <<<NBLK, SCAN_B>>>(E);
    k_fill   <<<EB, T>>>(ei, E);

    k_gemm_fused<<<NPAD / 128, 256, SM_WMMA>>>(X, b1, NN);

    k_gather_scalar<<<(NN + T - 1) / T, T>>>();
    k_pairs<<<(P + T - 1) / T, T>>>(bl, out, P);
}

// round 17
// speedup vs baseline: 1.3050x; 1.3050x over previous
#include <cuda_runtime.h>
#include <cuda_bf16.h>
#include <mma.h>
#include <math.h>
#include <stdint.h>

using namespace nvcuda;

#define NN 50000          // nodes
#define NPAD 50048        // padded to 128
#define NF 128            // feature width
#define NH 256            // hidden width
#define EMAX 800000
#define PMAX 100000
#define SCAN_B 1024
#define NBLK ((NN + SCAN_B - 1) / SCAN_B)   // 49

// ---- scratch (device globals; no allocation allowed) ----
__device__ int   g_eidx[EMAX];
__device__ int   g_cnt [NN + 64];           // tail [NN..NN+63] = scan flags
__device__ int   g_cur [NN];                // fill cursors (init = rowptr)
__device__ int   g_rowptr[NN + 1];
__device__ int   g_ma  [PMAX];
__device__ int   g_mb  [PMAX];
__device__ float g_dinv[NN];
__device__ __nv_bfloat16 g_Yh[(size_t)NPAD * NF];  // hi(S@X)
__device__ __nv_bfloat16 g_Yl[(size_t)NPAD * NF];  // lo(S@X)
__device__ __nv_bfloat16 g_Wh[(size_t)NF * NH];    // hi(W1)
__device__ __nv_bfloat16 g_Wl[(size_t)NF * NH];    // lo(W1)
__device__ float g_ta  [NN];                // relu(Y1@W1+b1) @ wa
__device__ float g_tb  [NN];
__device__ float g_u   [NN];
__device__ float g_v   [NN];
__device__ float g_wa  [NH];                // W2 @ Wl[0:128]
__device__ float g_wb  [NH];                // W2 @ Wl[128:256]
__device__ float g_ca, g_cb;

// ---------------------------------------------------- prologue kernels
// Per-thread dtype sniff: int64 node ids are all in [0, NN); int32 data
// viewed as int64 fuses random pairs into huge values. 8 samples => certain.
__device__ __forceinline__ int sniff_is64(const void* p_) {
    const long long* p = (const long long*)p_;
    int ok = 1;
#pragma unroll
    for (int i = 0; i < 8; i++) {
        long long v = p[i];
        if (v < 0 || v >= NN) ok = 0;
    }
    return ok;
}

// blocks [0,EB): edge degree count; [EB,EB+PB): mask; EB+PB: collapsed
// layer-2 weights; EB+PB+1: W1 bf16 hi/lo split
__global__ void k_convert(const void* __restrict__ ei, int E,
                          const void* __restrict__ mask, int P, int EB, int PB,
                          const float* __restrict__ W1,
                          const float* __restrict__ W2,
                          const float* __restrict__ b2,
                          const float* __restrict__ Wl) {
    int b = blockIdx.x;
    if (b < EB) {
        int e = b * blockDim.x + threadIdx.x;
        if (e >= E) return;
        int c;
        if (sniff_is64(ei)) c = (int)((const long long*)ei)[(size_t)E + e];
        else                c = ((const int*)ei)[E + e];
        atomicAdd(&g_cnt[c], 1);
    } else if (b < EB + PB) {
        int i = (b - EB) * blockDim.x + threadIdx.x;
        if (i >= P) return;
        int a, c;
        if (sniff_is64(mask)) {
            const long long* p = (const long long*)mask;
            a = (int)p[(size_t)i * 2 + 0];
            c = (int)p[(size_t)i * 2 + 1];
        } else {
            const int* p = (const int*)mask;
            a = p[i * 2 + 0];
            c = p[i * 2 + 1];
        }
        g_ma[i] = a;
        g_mb[i] = c;
    } else if (b == EB + PB) {
        // collapsed layer-2 weights: wa = W2@Wl_a, wb = W2@Wl_b, ca/cb
        int k = threadIdx.x;                // 0..255
        float sa = 0.f, sb = 0.f;
#pragma unroll 8
        for (int f = 0; f < NF; f++) {
            float w = W2[k * NF + f];
            sa += w * Wl[f];
            sb += w * Wl[NF + f];
        }
        g_wa[k] = sa;
        g_wb[k] = sb;
        __shared__ float ra[NH], rb[NH];
        ra[k] = (k < NF) ? b2[k] * Wl[k] : 0.f;
        rb[k] = (k < NF) ? b2[k] * Wl[NF + k] : 0.f;
        __syncthreads();
        for (int s = NH / 2; s > 0; s >>= 1) {
            if (k < s) { ra[k] += ra[k + s]; rb[k] += rb[k + s]; }
            __syncthreads();
        }
        if (k == 0) { g_ca = ra[0]; g_cb = rb[0]; }
    } else {
        // split W1 into bf16 hi/lo
        for (int idx = threadIdx.x; idx < NF * NH; idx += blockDim.x) {
            float v = W1[idx];
            __nv_bfloat16 h = __float2bfloat16(v);
            g_Wh[idx] = h;
            g_Wl[idx] = __float2bfloat16(v - __bfloat162float(h));
        }
    }
}

// --------------- fused scan: local scan + decoupled lookback + outputs
__global__ __launch_bounds__(SCAN_B)
void k_scan(int E) {
    __shared__ int sh[SCAN_B];
    __shared__ int sbase[32];
    int t = threadIdx.x;
    int b = blockIdx.x;
    int idx = b * SCAN_B + t;
    int v = (idx < NN) ? g_cnt[idx] : 0;
    sh[t] = v;
    __syncthreads();
    for (int off = 1; off < SCAN_B; off <<= 1) {
        int add = (t >= off) ? sh[t - off] : 0;
        __syncthreads();
        sh[t] += add;
        __syncthreads();
    }
    int excl = sh[t] - v;
    if (t == SCAN_B - 1)
        atomicExch(&g_cnt[NN + b], sh[t] + 1);
    int part = 0;
    if (t < b) {
        volatile int* f = &g_cnt[NN + t];
        int x;
        while ((x = *f) == 0) { }
        part = x - 1;
    }
    if (t < 64) {
#pragma unroll
        for (int o = 16; o > 0; o >>= 1)
            part += __shfl_xor_sync(0xffffffffu, part, o);
        if ((t & 31) == 0) sbase[t >> 5] = part;
    }
    __syncthreads();
    int base = sbase[0] + sbase[1];
    if (idx < NN) {
        int rp = excl + base;
        g_rowptr[idx] = rp;
        g_cur[idx]    = rp;
        g_dinv[idx]   = rsqrtf((float)g_cnt[idx] + 1.0f);
    }
    if (b == 0 && t == 0) g_rowptr[NN] = E;
}

// fill reads the raw edge buffer directly (no row/col scratch)
__global__ void k_fill(const void* __restrict__ ei, int E) {
    int e = blockIdx.x * blockDim.x + threadIdx.x;
    if (e >= E) return;
    int r, c;
    if (sniff_is64(ei)) {
        const long long* p = (const long long*)ei;
        r = (int)p[e];
        c = (int)p[(size_t)E + e];
    } else {
        const int* p = (const int*)ei;
        r = p[e];
        c = p[E + e];
    }
    int pos = atomicAdd(&g_cur[c], 1);
    g_eidx[pos] = r;
}

// --------------------------------------------- gather (emits bf16 hi/lo)
// HIGH-OCCUPANCY standalone kernel (measured at LTS cap, 33.4 us).
__global__ __launch_bounds__(256)
void k_gather(const float* __restrict__ src) {
    int node = (blockIdx.x * blockDim.x + threadIdx.x) >> 5;
    if (node >= NN) return;
    int lane = threadIdx.x & 31;
    float dc = g_dinv[node];

    float4 v = ((const float4*)(src + (size_t)node * NF))[lane];
    float ws = dc * dc;
    float4 acc;
    acc.x = ws * v.x; acc.y = ws * v.y; acc.z = ws * v.z; acc.w = ws * v.w;

    int beg = g_rowptr[node];
    int end = g_rowptr[node + 1];
#pragma unroll 4
    for (int j = beg; j < end; j++) {
        int r = __ldg(&g_eidx[j]);
        float w = __ldg(&g_dinv[r]) * dc;
        float4 u = ((const float4*)(src + (size_t)r * NF))[lane];
        acc.x += w * u.x; acc.y += w * u.y;
        acc.z += w * u.z; acc.w += w * u.w;
    }
    __nv_bfloat16 h0 = __float2bfloat16(acc.x);
    __nv_bfloat16 h1 = __float2bfloat16(acc.y);
    __nv_bfloat16 h2 = __float2bfloat16(acc.z);
    __nv_bfloat16 h3 = __float2bfloat16(acc.w);
    __nv_bfloat16 l0 = __float2bfloat16(acc.x - __bfloat162float(h0));
    __nv_bfloat16 l1 = __float2bfloat16(acc.y - __bfloat162float(h1));
    __nv_bfloat16 l2 = __float2bfloat16(acc.z - __bfloat162float(h2));
    __nv_bfloat16 l3 = __float2bfloat16(acc.w - __bfloat162float(h3));
    __nv_bfloat162 hp0 = __halves2bfloat162(h0, h1);
    __nv_bfloat162 hp1 = __halves2bfloat162(h2, h3);
    __nv_bfloat162 lp0 = __halves2bfloat162(l0, l1);
    __nv_bfloat162 lp1 = __halves2bfloat162(l2, l3);
    uint2 hv = make_uint2(*(uint32_t*)&hp0, *(uint32_t*)&hp1);
    uint2 lv = make_uint2(*(uint32_t*)&lp0, *(uint32_t*)&lp1);
    *(uint2*)(g_Yh + (size_t)node * NF + lane * 4) = hv;
    *(uint2*)(g_Yl + (size_t)node * NF + lane * 4) = lv;
}

// ==================== split-bf16 wmma GEMM + relu + dual dot
// CTA: 128 rows x 256 cols (two 128-col halves of B staged in turn).
// 512 threads = 16 warps as 4x4; warp tile 32x32. fp32 accum.
// D = Ah*Bh + Ah*Bl + Al*Bh. Plain stores to ta/tb.
#define LDA 136                              // bf16 elems per smem row (pad)
#define SM_A    (2 * 128 * LDA * 2)          // Ah + Al = 69632 B
#define SM_B    (2 * 128 * LDA * 2)          // Bh + Bl = 69632 B (also Csm)
#define SM_WMMA (SM_A + SM_B)                // 139264 B

__global__ __launch_bounds__(512, 1)
void k_gemm_wmma(const float* __restrict__ b1, int M) {
    extern __shared__ char smc[];
    __nv_bfloat16* Ah = (__nv_bfloat16*)smc;
    __nv_bfloat16* Al = Ah + 128 * LDA;
    __nv_bfloat16* Bh = (__nv_bfloat16*)(smc + SM_A);
    __nv_bfloat16* Bl = Bh + 128 * LDA;
    float* Csm = (float*)(smc + SM_A);       // overlays B after compute

    int tid = threadIdx.x;
    int rowBlock = blockIdx.x * 128;
    int w = tid >> 5;
    int wr = w >> 2, wc = w & 3;             // 4 row-groups x 4 col-groups
    int er = tid >> 2, eh = tid & 3;         // epilogue: 4 threads / row

    // stage A tile once
    for (int idx = tid; idx < 128 * 16; idx += 512) {
        int r = idx >> 4, c8 = (idx & 15) << 3;
        size_t g = (size_t)(rowBlock + r) * NF + c8;
        *(uint4*)(Ah + r * LDA + c8) = *(const uint4*)(g_Yh + g);
        *(uint4*)(Al + r * LDA + c8) = *(const uint4*)(g_Yl + g);
    }

    float da = 0.f, db = 0.f;

#pragma unroll
    for (int half = 0; half < 2; half++) {
        int colBlock = half * 128;
        for (int idx = tid; idx < 128 * 16; idx += 512) {
            int k = idx >> 4, c8 = (idx & 15) << 3;
            size_t g = (size_t)k * NH + colBlock + c8;
            *(uint4*)(Bh + k * LDA + c8) = *(const uint4*)(g_Wh + g);
            *(uint4*)(Bl + k * LDA + c8) = *(const uint4*)(g_Wl + g);
        }
        __syncthreads();

        wmma::fragment<wmma::accumulator, 16, 16, 16, float> C[2][2];
#pragma unroll
        for (int i = 0; i < 2; i++)
#pragma unroll
            for (int j = 0; j < 2; j++) wmma::fill_fragment(C[i][j], 0.0f);

        for (int ks = 0; ks < 128; ks += 16) {
            wmma::fragment<wmma::matrix_a, 16, 16, 16, __nv_bfloat16, wmma::row_major> ah[2], al[2];
            wmma::fragment<wmma::matrix_b, 16, 16, 16, __nv_bfloat16, wmma::row_major> bh[2], bl[2];
#pragma unroll
            for (int i = 0; i < 2; i++) {
                wmma::load_matrix_sync(ah[i], Ah + (wr * 32 + i * 16) * LDA + ks, LDA);
                wmma::load_matrix_sync(al[i], Al + (wr * 32 + i * 16) * LDA + ks, LDA);
            }
#pragma unroll
            for (int j = 0; j < 2; j++) {
                wmma::load_matrix_sync(bh[j], Bh + ks * LDA + wc * 32 + j * 16, LDA);
                wmma::load_matrix_sync(bl[j], Bl + ks * LDA + wc * 32 + j * 16, LDA);
            }
#pragma unroll
            for (int i = 0; i < 2; i++)
#pragma unroll
                for (int j = 0; j < 2; j++) {
                    wmma::mma_sync(C[i][j], ah[i], bh[j], C[i][j]);
                    wmma::mma_sync(C[i][j], ah[i], bl[j], C[i][j]);
                    wmma::mma_sync(C[i][j], al[i], bh[j], C[i][j]);
                }
        }
        __syncthreads();                      // B reads done

#pragma unroll
        for (int i = 0; i < 2; i++)
#pragma unroll
            for (int j = 0; j < 2; j++)
                wmma::store_matrix_sync(Csm + (wr * 32 + i * 16) * LDA + wc * 32 + j * 16,
                                        C[i][j], LDA, wmma::mem_row_major);
        __syncthreads();

        // epilogue: relu(C + b1) dot wa/wb; 4 threads/row, 32 cols each
        int cbase = eh * 32;
#pragma unroll 8
        for (int c = 0; c < 32; c++) {
            int col = colBlock + cbase + c;
            float vv = fmaxf(Csm[er * LDA + cbase + c] + __ldg(&b1[col]), 0.f);
            da += vv * g_wa[col];
            db += vv * g_wb[col];
        }
        __syncthreads();                      // Csm reads done (before restage)
    }

    da += __shfl_xor_sync(0xffffffffu, da, 1);
    db += __shfl_xor_sync(0xffffffffu, db, 1);
    da += __shfl_xor_sync(0xffffffffu, da, 2);
    db += __shfl_xor_sync(0xffffffffu, db, 2);
    if (eh == 0) {
        int row = rowBlock + er;
        if (row < M) { g_ta[row] = da; g_tb[row] = db; }
    }
}

// ------------------------------------------- scalar propagation (layer 2)
__global__ void k_gather_scalar() {
    int n = blockIdx.x * blockDim.x + threadIdx.x;
    if (n >= NN) return;
    float dc = g_dinv[n];
    float sa = dc * g_ta[n];
    float sb = dc * g_tb[n];
    int beg = g_rowptr[n], end = g_rowptr[n + 1];
    for (int j = beg; j < end; j++) {
        int r = __ldg(&g_eidx[j]);
        float w = __ldg(&g_dinv[r]);
        sa += w * __ldg(&g_ta[r]);
        sb += w * __ldg(&g_tb[r]);
    }
    g_u[n] = dc * sa + g_ca;
    g_v[n] = dc * sb + g_cb;
}

__global__ void k_pairs(const float* __restrict__ bl,
                        float* __restrict__ out, int P) {
    int p = blockIdx.x * blockDim.x + threadIdx.x;
    if (p >= P) return;
    float s = g_u[g_ma[p]] + g_v[g_mb[p]] + bl[0];
    out[p] = 1.0f / (1.0f + expf(-s));
}

// ------------------------------------------------------------------ launch
extern "C" void kernel_launch(void* const* d_in, const int* in_sizes, int n_in,
                              void* d_out, int out_size) {
    const void*  ei   = d_in[0];
    const float* X    = (const float*)d_in[1];
    const void*  mask = d_in[2];
    const float* W1   = (const float*)d_in[3];
    const float* b1   = (const float*)d_in[4];
    const float* W2   = (const float*)d_in[5];
    const float* b2   = (const float*)d_in[6];
    const float* Wl   = (const float*)d_in[7];
    const float* bl   = (const float*)d_in[8];
    float* out = (float*)d_out;

    int E = in_sizes[0] / 2;
    int P = out_size;

    cudaFuncSetAttribute(k_gemm_wmma,
                         cudaFuncAttributeMaxDynamicSharedMemorySize, SM_WMMA);

    void* cnt_addr = nullptr;
    cudaGetSymbolAddress(&cnt_addr, g_cnt);

    const int T = 256;
    int EB = (E + T - 1) / T;
    int PB = (P + T - 1) / T;

    // zero degree counts + scan flags in one async memset (graph-capturable)
    cudaMemsetAsync(cnt_addr, 0, sizeof(int) * (NN + 64), 0);

    k_convert<<<EB + PB + 2, T>>>(ei, E, mask, P, EB, PB, W1, W2, b2, Wl);
    k_scan   <<<NBLK, SCAN_B>>>(E);
    k_fill   <<<EB, T>>>(ei, E);

    k_gather<<<(NN * 32 + T - 1) / T, T>>>(X);
    k_gemm_wmma<<<NPAD / 128, 512, SM_WMMA>>>(b1, NN);

    k_gather_scalar<<<(NN + T - 1) / T, T>>>();
    k_pairs<<<(P + T - 1) / T, T>>>(bl, out, P);
}